// round 15
// baseline (speedup 1.0000x reference)
#include <cuda_runtime.h>
#include <cuda_bf16.h>
#include <cstdint>

// Problem constants (fixed by the dataset).
#define NN      50000
#define NE      1600000
#define IN_DIM  256
#define OUTF    128          // N_HEADS * OUT_DIM
#define NHEADS  4
#define HD      32           // OUT_DIM per head
#define ALPHA_SLOPE 0.2f

#define NB      ((NN + 255) / 256)        // 196 scan blocks
#define GB      ((NN + 127) / 128)        // 391 gemm blocks (1 tile each)
#define SB4     ((NE + 1023) / 1024)      // 1563 scatter blocks (4 edges/thread)
#define NE4     (NE / 4)                  // 400000 int4 edge quads

// Mega-kernel layout.  Dispatch order = block index order:
//   blocks 0..NB-1      : hist chunk -> wait hist(NB) -> scan -> gemm tile
//   blocks NB..GB-1     : pure gemm tile (no waits)
//   blocks GB..GB+SB4-1 : scatter (waits scan_done == NB)
// Deadlock safety: hist arrivals and waiters are BOTH exactly blocks 0..NB-1,
// which are the first dispatched and co-resident (launch_bounds(256,2) =>
// 2 blocks/SM => 296 slots >= 196).  Every arrive precedes the wait in
// program order, so all 196 arrive then all proceed.  Scatter waits only on
// those same resident blocks.
#define SCAT_BEG  GB
#define MEGA_GRID (GB + SB4)

// ---------------- scratch (device globals; no allocation allowed) -----------
// g_deg is zero at module load and re-zeroed by agg_kernel each launch
// (launch-boundary ordered).  Scan is READ-ONLY on deg — no intra-kernel race.
// g_hist_done/g_scan_done are reset by agg_kernel too.
__device__ float g_hprime[(size_t)NN * OUTF];     // 25.6 MB
__device__ float g_alpha_src[(size_t)NN * NHEADS];
__device__ float g_alpha_dst[(size_t)NN * NHEADS];
__device__ int   g_deg[NN];
__device__ int   g_row[NN];
__device__ int   g_cursor[NN];
__device__ int   g_src_sorted[NE];                // 6.4 MB
__device__ int   g_hist_done;
__device__ int   g_scan_done;

// ---------------- sync helpers ----------------------------------------------
__device__ __forceinline__ int ld_acquire(const int* p) {
    int v;
    asm volatile("ld.acquire.gpu.global.b32 %0, [%1];" : "=r"(v) : "l"(p));
    return v;
}
__device__ __forceinline__ void red_release_add(int* p, int v) {
    asm volatile("red.release.gpu.global.add.s32 [%0], %1;" :: "l"(p), "r"(v)
                 : "memory");
}
__device__ __forceinline__ void spin_until(const int* ctr, int target) {
    if (threadIdx.x == 0) {
        while (ld_acquire(ctr) < target) __nanosleep(128);
    }
    __syncthreads();
}

// ---------------- K1 mega ----------------------------------------------------
#define BM 128
#define BN 128
#define BK 16
#define TM 8
#define TN 8

#define FMA_F32X2(d, a, b, c) \
    asm("fma.rn.f32x2 %0, %1, %2, %3;" : "=l"(d) : "l"(a), "l"(b), "l"(c))

__global__ __launch_bounds__(256, 2)
void mega_kernel(const float* __restrict__ A, const float* __restrict__ B,
                 const float* __restrict__ av, float* __restrict__ C,
                 float* __restrict__ asrc, float* __restrict__ adst,
                 const int* __restrict__ adj, int* __restrict__ deg,
                 int* __restrict__ row, int* __restrict__ cursor,
                 int* __restrict__ srcs) {
    const int tid = threadIdx.x;           // 256 threads
    const int bid = blockIdx.x;

    if (bid >= SCAT_BEG) {
        // ================= scatter phase (waits on scan) =====================
        spin_until(&g_scan_done, NB);
        int base = (bid - SCAT_BEG) * 1024 + tid * 4;
        if (base < NE) {                   // NE % 4 == 0 -> full int4 in-range
            int4 s4 = *reinterpret_cast<const int4*>(adj + base);
            int4 d4 = *reinterpret_cast<const int4*>(adj + NE + base);
            int p0 = atomicAdd(&cursor[d4.x], 1); srcs[p0] = s4.x;
            int p1 = atomicAdd(&cursor[d4.y], 1); srcs[p1] = s4.y;
            int p2 = atomicAdd(&cursor[d4.z], 1); srcs[p2] = s4.z;
            int p3 = atomicAdd(&cursor[d4.w], 1); srcs[p3] = s4.w;
        }
        return;
    }

    // ===== blocks 0..NB-1: hist chunk -> barrier(hist) -> scan block bid =====
    if (bid < NB) {
        for (int i = bid * 256 + tid; i < NE4; i += NB * 256) {
            int4 d4 = *reinterpret_cast<const int4*>(adj + NE + i * 4);
            atomicAdd(&deg[d4.x], 1);
            atomicAdd(&deg[d4.y], 1);
            atomicAdd(&deg[d4.z], 1);
            atomicAdd(&deg[d4.w], 1);
        }
        __syncthreads();
        if (tid == 0) red_release_add(&g_hist_done, 1);
        spin_until(&g_hist_done, NB);      // arrivals==waiters==blocks 0..NB-1

        // ---- scan block `bid` (READ-ONLY on deg) ----
        const int b = bid;
        const int lane = tid & 31, wid = tid >> 5;
        __shared__ int ws[8];
        __shared__ int s_boff;

        int pre = 0;
        for (int k = 0; k < b; k++) pre += deg[k * 256 + tid];
        int r = pre;
#pragma unroll
        for (int o = 16; o > 0; o >>= 1) r += __shfl_down_sync(0xffffffffu, r, o);
        if (lane == 0) ws[wid] = r;
        __syncthreads();
        if (tid == 0) {
            int s = 0;
#pragma unroll
            for (int w = 0; w < 8; w++) s += ws[w];
            s_boff = s;
        }
        __syncthreads();
        const int boff = s_boff;
        __syncthreads();                   // ws reused

        int i = b * 256 + tid;
        int v = (i < NN) ? deg[i] : 0;
        int x = v;
#pragma unroll
        for (int o = 1; o < 32; o <<= 1) {
            int y = __shfl_up_sync(0xffffffffu, x, o);
            if (lane >= o) x += y;
        }
        if (lane == 31) ws[wid] = x;
        __syncthreads();
        if (wid == 0 && lane < 8) {
            int w = ws[lane];
#pragma unroll
            for (int o = 1; o < 8; o <<= 1) {
                int y = __shfl_up_sync(0x000000ffu, w, o);
                if (lane >= o) w += y;
            }
            ws[lane] = w;
        }
        __syncthreads();
        int excl = x - v + (wid > 0 ? ws[wid - 1] : 0) + boff;
        if (i < NN) {
            row[i]    = excl;
            cursor[i] = excl;
            // deg NOT zeroed here (agg_kernel does it; avoids prefix-read race)
        }
        __syncthreads();
        if (tid == 0) red_release_add(&g_scan_done, 1);
        __syncthreads();                   // smem handoff to gemm section
    }

    // ==================== GEMM tile `bid` + fused alpha ======================
    __shared__ float As[BK][BM + 4];
    __shared__ float Bs[BK][BN];

    const int m0 = bid * BM;
    const int ty = tid >> 4;               // 0..15
    const int tx = tid & 15;               // 0..15

    unsigned long long accp[TM][TN / 2];
#pragma unroll
    for (int i = 0; i < TM; i++)
#pragma unroll
        for (int j = 0; j < TN / 2; j++) accp[i][j] = 0ull;

    for (int kt = 0; kt < IN_DIM; kt += BK) {
#pragma unroll
        for (int it = 0; it < 2; it++) {
            int idx = tid + it * 256;      // 0..511
            int rrow = idx >> 2;           // 0..127
            int c4   = (idx & 3) * 4;      // 0,4,8,12
            float4 v = make_float4(0.f, 0.f, 0.f, 0.f);
            int grow = m0 + rrow;
            if (grow < NN)
                v = *reinterpret_cast<const float4*>(
                    A + (size_t)grow * IN_DIM + kt + c4);
            As[c4 + 0][rrow] = v.x;
            As[c4 + 1][rrow] = v.y;
            As[c4 + 2][rrow] = v.z;
            As[c4 + 3][rrow] = v.w;
        }
#pragma unroll
        for (int it = 0; it < 2; it++) {
            int idx = tid + it * 256;
            int rrow = idx >> 5;           // 0..15
            int col  = (idx & 31) * 4;
            *reinterpret_cast<float4*>(&Bs[rrow][col]) =
                *reinterpret_cast<const float4*>(B + (size_t)(kt + rrow) * BN + col);
        }
        __syncthreads();

#pragma unroll
        for (int k = 0; k < BK; k++) {
            float4 a0 = *reinterpret_cast<const float4*>(&As[k][ty * TM]);
            float4 a1 = *reinterpret_cast<const float4*>(&As[k][ty * TM + 4]);
            ulonglong2 b01 = *reinterpret_cast<const ulonglong2*>(&Bs[k][tx * TN]);
            ulonglong2 b23 = *reinterpret_cast<const ulonglong2*>(&Bs[k][tx * TN + 4]);
            float ra[TM] = {a0.x, a0.y, a0.z, a0.w, a1.x, a1.y, a1.z, a1.w};
#pragma unroll
            for (int i = 0; i < TM; i++) {
                unsigned long long a2;
                unsigned int rbits = __float_as_uint(ra[i]);
                asm("mov.b64 %0, {%1, %1};" : "=l"(a2) : "r"(rbits));
                FMA_F32X2(accp[i][0], a2, b01.x, accp[i][0]);
                FMA_F32X2(accp[i][1], a2, b01.y, accp[i][1]);
                FMA_F32X2(accp[i][2], a2, b23.x, accp[i][2]);
                FMA_F32X2(accp[i][3], a2, b23.y, accp[i][3]);
            }
        }
        __syncthreads();
    }

    // epilogue: store C tile + fused alpha dot products
    const int h      = tx >> 2;
    const int d_base = (tx & 3) * 8;
    float avs[TN], avd[TN];
#pragma unroll
    for (int j = 0; j < TN; j++) {
        avs[j] = __ldg(&av[(d_base + j) * NHEADS + h]);
        avd[j] = __ldg(&av[(32 + d_base + j) * NHEADS + h]);
    }

#pragma unroll
    for (int i = 0; i < TM; i++) {
        int grow = m0 + ty * TM + i;
        const float* f = reinterpret_cast<const float*>(accp[i]);
        if (grow < NN) {
            float4 v0 = make_float4(f[0], f[1], f[2], f[3]);
            float4 v1 = make_float4(f[4], f[5], f[6], f[7]);
            *reinterpret_cast<float4*>(C + (size_t)grow * BN + tx * TN)     = v0;
            *reinterpret_cast<float4*>(C + (size_t)grow * BN + tx * TN + 4) = v1;
        }
        float s = 0.f, t = 0.f;
#pragma unroll
        for (int j = 0; j < TN; j++) {
            s += f[j] * avs[j];
            t += f[j] * avd[j];
        }
        s += __shfl_xor_sync(0xffffffffu, s, 1);
        s += __shfl_xor_sync(0xffffffffu, s, 2);
        t += __shfl_xor_sync(0xffffffffu, t, 1);
        t += __shfl_xor_sync(0xffffffffu, t, 2);
        if (grow < NN && (tx & 3) == 0) {
            asrc[(size_t)grow * NHEADS + h] = s;
            adst[(size_t)grow * NHEADS + h] = t;
        }
    }
}

// ---------------- K2: warp-per-node softmax + aggregation (no atomics) ------
// Lane l owns output floats [4l, 4l+4); head = l>>3.  Edge loop unrolled x2
// (measured optimum).  Degree = cursor[n] - row[n].  Also zeroes deg[] and
// resets the mega counters for the next launch (launch-boundary ordered).
__global__ __launch_bounds__(256)
void agg_kernel(const int* __restrict__ row, const int* __restrict__ cur,
                const int* __restrict__ srcs,
                const float* __restrict__ asrc, const float* __restrict__ adst,
                const float* __restrict__ hp, float* __restrict__ out,
                int* __restrict__ deg) {
    int gid = blockIdx.x * blockDim.x + threadIdx.x;
    if (gid < NN) deg[gid] = 0;            // clean histogram for next launch
    if (gid == 0) {
        g_hist_done = 0;
        g_scan_done = 0;
    }

    int n = gid >> 5;
    if (n >= NN) return;
    int lane = threadIdx.x & 31;
    int head = lane >> 3;

    int beg = row[n];
    int dn  = cur[n] - beg;
    float au = __ldg(&adst[n * NHEADS + head]);

    float accx = 0.f, accy = 0.f, accz = 0.f, accw = 0.f;
    float ssum = 0.f;

    int j = 0;
    for (; j + 2 <= dn; j += 2) {
        int s0 = __ldg(&srcs[beg + j]);
        int s1 = __ldg(&srcs[beg + j + 1]);
        float v0 = __ldg(&asrc[s0 * NHEADS + head]) + au;
        float v1 = __ldg(&asrc[s1 * NHEADS + head]) + au;
        const float4 h0 = *reinterpret_cast<const float4*>(
            hp + (size_t)s0 * OUTF + lane * 4);
        const float4 h1 = *reinterpret_cast<const float4*>(
            hp + (size_t)s1 * OUTF + lane * 4);
        v0 = v0 > 0.f ? v0 : ALPHA_SLOPE * v0;
        v1 = v1 > 0.f ? v1 : ALPHA_SLOPE * v1;
        float e0 = __expf(v0);             // softmax shift-invariant; |v| small
        float e1 = __expf(v1);
        ssum += e0 + e1;
        accx += e0 * h0.x + e1 * h1.x;
        accy += e0 * h0.y + e1 * h1.y;
        accz += e0 * h0.z + e1 * h1.z;
        accw += e0 * h0.w + e1 * h1.w;
    }
    if (j < dn) {
        int s0 = __ldg(&srcs[beg + j]);
        float v0 = __ldg(&asrc[s0 * NHEADS + head]) + au;
        const float4 h0 = *reinterpret_cast<const float4*>(
            hp + (size_t)s0 * OUTF + lane * 4);
        v0 = v0 > 0.f ? v0 : ALPHA_SLOPE * v0;
        float e0 = __expf(v0);
        ssum += e0;
        accx += e0 * h0.x;
        accy += e0 * h0.y;
        accz += e0 * h0.z;
        accw += e0 * h0.w;
    }
    if (dn > 0) {
        float inv = 1.0f / ssum;
        accx *= inv; accy *= inv; accz *= inv; accw *= inv;
    }
    *reinterpret_cast<float4*>(out + (size_t)n * OUTF + lane * 4) =
        make_float4(accx, accy, accz, accw);
}

// ---------------- launch ----------------------------------------------------
extern "C" void kernel_launch(void* const* d_in, const int* in_sizes, int n_in,
                              void* d_out, int out_size) {
    const float* h   = (const float*)d_in[0];   // [50000, 256]
    const int*   adj = (const int*)  d_in[1];   // [2, 1600000]
    const float* W   = (const float*)d_in[2];   // [256, 128]
    const float* a   = (const float*)d_in[3];   // [64, 4]
    float*       out = (float*)d_out;           // [50000, 128]

    void *p_hp, *p_as, *p_ad, *p_deg, *p_row, *p_cur, *p_srcs;
    cudaGetSymbolAddress(&p_hp,   g_hprime);
    cudaGetSymbolAddress(&p_as,   g_alpha_src);
    cudaGetSymbolAddress(&p_ad,   g_alpha_dst);
    cudaGetSymbolAddress(&p_deg,  g_deg);
    cudaGetSymbolAddress(&p_row,  g_row);
    cudaGetSymbolAddress(&p_cur,  g_cursor);
    cudaGetSymbolAddress(&p_srcs, g_src_sorted);

    // 1) one launch: blocks 0..195 do hist+scan then their gemm tile;
    //    blocks 196..390 pure gemm; scatter blocks wait on scan only.
    mega_kernel<<<MEGA_GRID, 256>>>(h, W, a, (float*)p_hp,
                                    (float*)p_as, (float*)p_ad,
                                    adj, (int*)p_deg,
                                    (int*)p_row, (int*)p_cur, (int*)p_srcs);

    // 2) warp-per-node gather softmax-aggregate (+ deg re-zero, counter reset)
    agg_kernel<<<(NN * 32 + 255) / 256, 256>>>(
        (const int*)p_row, (const int*)p_cur, (const int*)p_srcs,
        (const float*)p_as, (const float*)p_ad, (const float*)p_hp, out,
        (int*)p_deg);
}

// round 16
// speedup vs baseline: 1.0251x; 1.0251x over previous
#include <cuda_runtime.h>
#include <cuda_bf16.h>
#include <cuda_fp16.h>
#include <cstdint>

// Problem constants (fixed by the dataset).
#define NN      50000
#define NE      1600000
#define IN_DIM  256
#define OUTF    128          // N_HEADS * OUT_DIM
#define NHEADS  4
#define HD      32           // OUT_DIM per head
#define ALPHA_SLOPE 0.2f

#define NB      ((NN + 255) / 256)        // 196 scan blocks
#define GB      ((NN + 127) / 128)        // 391 gemm blocks (1 tile each)
#define SB4     ((NE + 1023) / 1024)      // 1563 scatter blocks (4 edges/thread)
#define NE4     (NE / 4)                  // 400000 int4 edge quads

// Mega-kernel layout.  Dispatch order = block index order:
//   blocks 0..NB-1      : hist chunk -> wait hist(NB) -> scan -> gemm tile
//   blocks NB..GB-1     : pure gemm tile (no waits)
//   blocks GB..GB+SB4-1 : scatter (waits scan_done == NB)
// Deadlock safety: hist arrivals and waiters are BOTH exactly blocks 0..NB-1
// (first dispatched, co-resident: launch_bounds(256,2) => 296 slots >= 196).
#define SCAT_BEG  GB
#define MEGA_GRID (GB + SB4)

// ---------------- scratch (device globals; no allocation allowed) -----------
// g_deg is zero at module load and re-zeroed by agg_kernel each launch.
// Scan is READ-ONLY on deg.  h_prime is stored fp16 ONLY (12.8 MB): the
// attention scalars are fp32-exact (computed from fp32 registers in the GEMM
// epilogue); only the aggregated feature values quantize (~3e-4 rel).
__device__ __half g_hprime_h[(size_t)NN * OUTF]; // 12.8 MB
__device__ float g_alpha_src[(size_t)NN * NHEADS];
__device__ float g_alpha_dst[(size_t)NN * NHEADS];
__device__ int   g_deg[NN];
__device__ int   g_row[NN];
__device__ int   g_cursor[NN];
__device__ int   g_src_sorted[NE];                // 6.4 MB
__device__ int   g_hist_done;
__device__ int   g_scan_done;

// ---------------- sync helpers ----------------------------------------------
__device__ __forceinline__ int ld_acquire(const int* p) {
    int v;
    asm volatile("ld.acquire.gpu.global.b32 %0, [%1];" : "=r"(v) : "l"(p));
    return v;
}
__device__ __forceinline__ void red_release_add(int* p, int v) {
    asm volatile("red.release.gpu.global.add.s32 [%0], %1;" :: "l"(p), "r"(v)
                 : "memory");
}
__device__ __forceinline__ void spin_until(const int* ctr, int target) {
    if (threadIdx.x == 0) {
        while (ld_acquire(ctr) < target) __nanosleep(128);
    }
    __syncthreads();
}

// ---------------- K1 mega ----------------------------------------------------
#define BM 128
#define BN 128
#define BK 16
#define TM 8
#define TN 8

#define FMA_F32X2(d, a, b, c) \
    asm("fma.rn.f32x2 %0, %1, %2, %3;" : "=l"(d) : "l"(a), "l"(b), "l"(c))

__global__ __launch_bounds__(256, 2)
void mega_kernel(const float* __restrict__ A, const float* __restrict__ B,
                 const float* __restrict__ av, __half* __restrict__ Ch,
                 float* __restrict__ asrc, float* __restrict__ adst,
                 const int* __restrict__ adj, int* __restrict__ deg,
                 int* __restrict__ row, int* __restrict__ cursor,
                 int* __restrict__ srcs) {
    const int tid = threadIdx.x;           // 256 threads
    const int bid = blockIdx.x;

    if (bid >= SCAT_BEG) {
        // ================= scatter phase (waits on scan) =====================
        spin_until(&g_scan_done, NB);
        int base = (bid - SCAT_BEG) * 1024 + tid * 4;
        if (base < NE) {                   // NE % 4 == 0 -> full int4 in-range
            int4 s4 = *reinterpret_cast<const int4*>(adj + base);
            int4 d4 = *reinterpret_cast<const int4*>(adj + NE + base);
            int p0 = atomicAdd(&cursor[d4.x], 1); srcs[p0] = s4.x;
            int p1 = atomicAdd(&cursor[d4.y], 1); srcs[p1] = s4.y;
            int p2 = atomicAdd(&cursor[d4.z], 1); srcs[p2] = s4.z;
            int p3 = atomicAdd(&cursor[d4.w], 1); srcs[p3] = s4.w;
        }
        return;
    }

    // ===== blocks 0..NB-1: hist chunk -> barrier(hist) -> scan block bid =====
    if (bid < NB) {
        for (int i = bid * 256 + tid; i < NE4; i += NB * 256) {
            int4 d4 = *reinterpret_cast<const int4*>(adj + NE + i * 4);
            atomicAdd(&deg[d4.x], 1);
            atomicAdd(&deg[d4.y], 1);
            atomicAdd(&deg[d4.z], 1);
            atomicAdd(&deg[d4.w], 1);
        }
        __syncthreads();
        if (tid == 0) red_release_add(&g_hist_done, 1);
        spin_until(&g_hist_done, NB);      // arrivals==waiters==blocks 0..NB-1

        // ---- scan block `bid` (READ-ONLY on deg) ----
        const int b = bid;
        const int lane = tid & 31, wid = tid >> 5;
        __shared__ int ws[8];
        __shared__ int s_boff;

        int pre = 0;
        for (int k = 0; k < b; k++) pre += deg[k * 256 + tid];
        int r = pre;
#pragma unroll
        for (int o = 16; o > 0; o >>= 1) r += __shfl_down_sync(0xffffffffu, r, o);
        if (lane == 0) ws[wid] = r;
        __syncthreads();
        if (tid == 0) {
            int s = 0;
#pragma unroll
            for (int w = 0; w < 8; w++) s += ws[w];
            s_boff = s;
        }
        __syncthreads();
        const int boff = s_boff;
        __syncthreads();                   // ws reused

        int i = b * 256 + tid;
        int v = (i < NN) ? deg[i] : 0;
        int x = v;
#pragma unroll
        for (int o = 1; o < 32; o <<= 1) {
            int y = __shfl_up_sync(0xffffffffu, x, o);
            if (lane >= o) x += y;
        }
        if (lane == 31) ws[wid] = x;
        __syncthreads();
        if (wid == 0 && lane < 8) {
            int w = ws[lane];
#pragma unroll
            for (int o = 1; o < 8; o <<= 1) {
                int y = __shfl_up_sync(0x000000ffu, w, o);
                if (lane >= o) w += y;
            }
            ws[lane] = w;
        }
        __syncthreads();
        int excl = x - v + (wid > 0 ? ws[wid - 1] : 0) + boff;
        if (i < NN) {
            row[i]    = excl;
            cursor[i] = excl;
            // deg NOT zeroed here (agg_kernel does it; avoids prefix-read race)
        }
        __syncthreads();
        if (tid == 0) red_release_add(&g_scan_done, 1);
        __syncthreads();                   // smem handoff to gemm section
    }

    // ==================== GEMM tile `bid` + fused alpha ======================
    __shared__ float As[BK][BM + 4];
    __shared__ float Bs[BK][BN];

    const int m0 = bid * BM;
    const int ty = tid >> 4;               // 0..15
    const int tx = tid & 15;               // 0..15

    unsigned long long accp[TM][TN / 2];
#pragma unroll
    for (int i = 0; i < TM; i++)
#pragma unroll
        for (int j = 0; j < TN / 2; j++) accp[i][j] = 0ull;

    for (int kt = 0; kt < IN_DIM; kt += BK) {
#pragma unroll
        for (int it = 0; it < 2; it++) {
            int idx = tid + it * 256;      // 0..511
            int rrow = idx >> 2;           // 0..127
            int c4   = (idx & 3) * 4;      // 0,4,8,12
            float4 v = make_float4(0.f, 0.f, 0.f, 0.f);
            int grow = m0 + rrow;
            if (grow < NN)
                v = *reinterpret_cast<const float4*>(
                    A + (size_t)grow * IN_DIM + kt + c4);
            As[c4 + 0][rrow] = v.x;
            As[c4 + 1][rrow] = v.y;
            As[c4 + 2][rrow] = v.z;
            As[c4 + 3][rrow] = v.w;
        }
#pragma unroll
        for (int it = 0; it < 2; it++) {
            int idx = tid + it * 256;
            int rrow = idx >> 5;           // 0..15
            int col  = (idx & 31) * 4;
            *reinterpret_cast<float4*>(&Bs[rrow][col]) =
                *reinterpret_cast<const float4*>(B + (size_t)(kt + rrow) * BN + col);
        }
        __syncthreads();

#pragma unroll
        for (int k = 0; k < BK; k++) {
            float4 a0 = *reinterpret_cast<const float4*>(&As[k][ty * TM]);
            float4 a1 = *reinterpret_cast<const float4*>(&As[k][ty * TM + 4]);
            ulonglong2 b01 = *reinterpret_cast<const ulonglong2*>(&Bs[k][tx * TN]);
            ulonglong2 b23 = *reinterpret_cast<const ulonglong2*>(&Bs[k][tx * TN + 4]);
            float ra[TM] = {a0.x, a0.y, a0.z, a0.w, a1.x, a1.y, a1.z, a1.w};
#pragma unroll
            for (int i = 0; i < TM; i++) {
                unsigned long long a2;
                unsigned int rbits = __float_as_uint(ra[i]);
                asm("mov.b64 %0, {%1, %1};" : "=l"(a2) : "r"(rbits));
                FMA_F32X2(accp[i][0], a2, b01.x, accp[i][0]);
                FMA_F32X2(accp[i][1], a2, b01.y, accp[i][1]);
                FMA_F32X2(accp[i][2], a2, b23.x, accp[i][2]);
                FMA_F32X2(accp[i][3], a2, b23.y, accp[i][3]);
            }
        }
        __syncthreads();
    }

    // epilogue: store fp16 h_prime tile + fused fp32 alpha dot products
    const int h      = tx >> 2;
    const int d_base = (tx & 3) * 8;
    float avs[TN], avd[TN];
#pragma unroll
    for (int j = 0; j < TN; j++) {
        avs[j] = __ldg(&av[(d_base + j) * NHEADS + h]);
        avd[j] = __ldg(&av[(32 + d_base + j) * NHEADS + h]);
    }

#pragma unroll
    for (int i = 0; i < TM; i++) {
        int grow = m0 + ty * TM + i;
        const float* f = reinterpret_cast<const float*>(accp[i]);
        if (grow < NN) {
            // 8 floats -> 4 half2 -> one 16B store (tx*8 halfs = 16B aligned)
            __half2 h0 = __floats2half2_rn(f[0], f[1]);
            __half2 h1 = __floats2half2_rn(f[2], f[3]);
            __half2 h2 = __floats2half2_rn(f[4], f[5]);
            __half2 h3 = __floats2half2_rn(f[6], f[7]);
            uint4 pk;
            pk.x = *reinterpret_cast<const uint32_t*>(&h0);
            pk.y = *reinterpret_cast<const uint32_t*>(&h1);
            pk.z = *reinterpret_cast<const uint32_t*>(&h2);
            pk.w = *reinterpret_cast<const uint32_t*>(&h3);
            *reinterpret_cast<uint4*>(Ch + (size_t)grow * OUTF + tx * TN) = pk;
        }
        float s = 0.f, t = 0.f;
#pragma unroll
        for (int j = 0; j < TN; j++) {
            s += f[j] * avs[j];
            t += f[j] * avd[j];
        }
        s += __shfl_xor_sync(0xffffffffu, s, 1);
        s += __shfl_xor_sync(0xffffffffu, s, 2);
        t += __shfl_xor_sync(0xffffffffu, t, 1);
        t += __shfl_xor_sync(0xffffffffu, t, 2);
        if (grow < NN && (tx & 3) == 0) {
            asrc[(size_t)grow * NHEADS + h] = s;
            adst[(size_t)grow * NHEADS + h] = t;
        }
    }
}

// ---------------- K2: warp-per-node softmax + aggregation (no atomics) ------
// Lane l owns output floats [4l, 4l+4); head = l>>3.  Edge loop unrolled x2
// (measured optimum).  h_prime gathered as fp16 (8B/lane/edge; weights stay
// fp32-exact).  Degree = cursor[n] - row[n].  Zeroes deg[] and resets the
// mega counters for the next launch (launch-boundary ordered).
__global__ __launch_bounds__(256)
void agg_kernel(const int* __restrict__ row, const int* __restrict__ cur,
                const int* __restrict__ srcs,
                const float* __restrict__ asrc, const float* __restrict__ adst,
                const __half* __restrict__ hp, float* __restrict__ out,
                int* __restrict__ deg) {
    int gid = blockIdx.x * blockDim.x + threadIdx.x;
    if (gid < NN) deg[gid] = 0;            // clean histogram for next launch
    if (gid == 0) {
        g_hist_done = 0;
        g_scan_done = 0;
    }

    int n = gid >> 5;
    if (n >= NN) return;
    int lane = threadIdx.x & 31;
    int head = lane >> 3;

    int beg = row[n];
    int dn  = cur[n] - beg;
    float au = __ldg(&adst[n * NHEADS + head]);

    float accx = 0.f, accy = 0.f, accz = 0.f, accw = 0.f;
    float ssum = 0.f;

    int j = 0;
    for (; j + 2 <= dn; j += 2) {
        int s0 = __ldg(&srcs[beg + j]);
        int s1 = __ldg(&srcs[beg + j + 1]);
        float v0 = __ldg(&asrc[s0 * NHEADS + head]) + au;
        float v1 = __ldg(&asrc[s1 * NHEADS + head]) + au;
        uint2 r0 = *reinterpret_cast<const uint2*>(hp + (size_t)s0 * OUTF + lane * 4);
        uint2 r1 = *reinterpret_cast<const uint2*>(hp + (size_t)s1 * OUTF + lane * 4);
        float2 a01 = __half22float2(*reinterpret_cast<const __half2*>(&r0.x));
        float2 a23 = __half22float2(*reinterpret_cast<const __half2*>(&r0.y));
        float2 b01 = __half22float2(*reinterpret_cast<const __half2*>(&r1.x));
        float2 b23 = __half22float2(*reinterpret_cast<const __half2*>(&r1.y));
        v0 = v0 > 0.f ? v0 : ALPHA_SLOPE * v0;
        v1 = v1 > 0.f ? v1 : ALPHA_SLOPE * v1;
        float e0 = __expf(v0);             // softmax shift-invariant; |v| small
        float e1 = __expf(v1);
        ssum += e0 + e1;
        accx += e0 * a01.x + e1 * b01.x;
        accy += e0 * a01.y + e1 * b01.y;
        accz += e0 * a23.x + e1 * b23.x;
        accw += e0 * a23.y + e1 * b23.y;
    }
    if (j < dn) {
        int s0 = __ldg(&srcs[beg + j]);
        float v0 = __ldg(&asrc[s0 * NHEADS + head]) + au;
        uint2 r0 = *reinterpret_cast<const uint2*>(hp + (size_t)s0 * OUTF + lane * 4);
        float2 a01 = __half22float2(*reinterpret_cast<const __half2*>(&r0.x));
        float2 a23 = __half22float2(*reinterpret_cast<const __half2*>(&r0.y));
        v0 = v0 > 0.f ? v0 : ALPHA_SLOPE * v0;
        float e0 = __expf(v0);
        ssum += e0;
        accx += e0 * a01.x;
        accy += e0 * a01.y;
        accz += e0 * a23.x;
        accw += e0 * a23.y;
    }
    if (dn > 0) {
        float inv = 1.0f / ssum;
        accx *= inv; accy *= inv; accz *= inv; accw *= inv;
    }
    *reinterpret_cast<float4*>(out + (size_t)n * OUTF + lane * 4) =
        make_float4(accx, accy, accz, accw);
}

// ---------------- launch ----------------------------------------------------
extern "C" void kernel_launch(void* const* d_in, const int* in_sizes, int n_in,
                              void* d_out, int out_size) {
    const float* h   = (const float*)d_in[0];   // [50000, 256]
    const int*   adj = (const int*)  d_in[1];   // [2, 1600000]
    const float* W   = (const float*)d_in[2];   // [256, 128]
    const float* a   = (const float*)d_in[3];   // [64, 4]
    float*       out = (float*)d_out;           // [50000, 128]

    void *p_hph, *p_as, *p_ad, *p_deg, *p_row, *p_cur, *p_srcs;
    cudaGetSymbolAddress(&p_hph,  g_hprime_h);
    cudaGetSymbolAddress(&p_as,   g_alpha_src);
    cudaGetSymbolAddress(&p_ad,   g_alpha_dst);
    cudaGetSymbolAddress(&p_deg,  g_deg);
    cudaGetSymbolAddress(&p_row,  g_row);
    cudaGetSymbolAddress(&p_cur,  g_cursor);
    cudaGetSymbolAddress(&p_srcs, g_src_sorted);

    // 1) one launch: blocks 0..195 do hist+scan then their gemm tile;
    //    blocks 196..390 pure gemm; scatter blocks wait on scan only.
    mega_kernel<<<MEGA_GRID, 256>>>(h, W, a, (__half*)p_hph,
                                    (float*)p_as, (float*)p_ad,
                                    adj, (int*)p_deg,
                                    (int*)p_row, (int*)p_cur, (int*)p_srcs);

    // 2) warp-per-node gather softmax-aggregate (+ deg re-zero, counter reset)
    agg_kernel<<<(NN * 32 + 255) / 256, 256>>>(
        (const int*)p_row, (const int*)p_cur, (const int*)p_srcs,
        (const float*)p_as, (const float*)p_ad, (const __half*)p_hph, out,
        (int*)p_deg);
}